// round 17
// baseline (speedup 1.0000x reference)
#include <cuda_runtime.h>
#include <cuda_fp16.h>
#include <math.h>
#include <stdint.h>

// Problem constants
constexpr int kB = 2, kT = 2048, kE = 1024, kH = 16, kD = 64;
constexpr float LAMBDA_INIT = 0.47071301834358415f;   // 0.8 - 0.6*exp(-0.6)
constexpr float LOG2E       = 1.4426950408889634f;
constexpr float QSCALE      = 0.125f * LOG2E;         // D^-0.5 folded with log2e
constexpr float EPS         = 1e-5f;

// Scratch (device globals; allocation is forbidden)
__device__ __half g_q1[kB * kH * kT * kD];
__device__ __half g_k1[kB * kH * kT * kD];
__device__ __half g_q2[kB * kH * kT * kD];
__device__ __half g_k2[kB * kH * kT * kD];
__device__ __half g_v [kB * kH * kT * kD];
__device__ __half g_attn[kB * kT * kE];
__device__ __half g_nh[kB * kT * kE];
__device__ __half g_xh[kB * kT * kE];
__device__ __half g_wq1[kE * kE], g_wk1[kE * kE], g_wq2[kE * kE];
__device__ __half g_wk2[kE * kE], g_wv[kE * kE], g_wo[kE * kE];
__device__ float g_pv1[kB * kH * kT * kD];   // unnormalized P1@V
__device__ float g_pv2[kB * kH * kT * kD];   // unnormalized P2@V
__device__ float g_l1[kB * kH * kT];         // softmax denominators
__device__ float g_l2[kB * kH * kT];
__device__ float g_lambda;

// ---------------------------------------------------------------------------
// helpers
// ---------------------------------------------------------------------------
__device__ __forceinline__ uint32_t pack_h2(float a, float b) {
    __half2 h = __floats2half2_rn(a, b);
    return *reinterpret_cast<uint32_t*>(&h);
}

__device__ __forceinline__ float ex2f(float x) {
    float r;
    asm("ex2.approx.ftz.f32 %0, %1;" : "=f"(r) : "f"(x));
    return r;
}

__device__ __forceinline__ void mma_f16(float* c, const uint32_t* a, const uint32_t* b) {
    asm volatile(
        "mma.sync.aligned.m16n8k16.row.col.f32.f16.f16.f32 "
        "{%0,%1,%2,%3}, {%4,%5,%6,%7}, {%8,%9}, {%0,%1,%2,%3};"
        : "+f"(c[0]), "+f"(c[1]), "+f"(c[2]), "+f"(c[3])
        : "r"(a[0]), "r"(a[1]), "r"(a[2]), "r"(a[3]), "r"(b[0]), "r"(b[1]));
}

__device__ __forceinline__ void ldsm_x4(uint32_t& r0, uint32_t& r1, uint32_t& r2,
                                        uint32_t& r3, uint32_t addr) {
    asm volatile("ldmatrix.sync.aligned.m8n8.x4.shared.b16 {%0,%1,%2,%3}, [%4];"
                 : "=r"(r0), "=r"(r1), "=r"(r2), "=r"(r3) : "r"(addr));
}

__device__ __forceinline__ void ldsm_x4_t(uint32_t& r0, uint32_t& r1, uint32_t& r2,
                                          uint32_t& r3, uint32_t addr) {
    asm volatile("ldmatrix.sync.aligned.m8n8.x4.trans.shared.b16 {%0,%1,%2,%3}, [%4];"
                 : "=r"(r0), "=r"(r1), "=r"(r2), "=r"(r3) : "r"(addr));
}

#define CP_ASYNC16(dst, src) \
    asm volatile("cp.async.cg.shared.global [%0], [%1], 16;" :: "r"(dst), "l"(src))
#define CP_COMMIT() asm volatile("cp.async.commit_group;")

// ---------------------------------------------------------------------------
// All fp32 -> fp16 conversions in ONE launch.
// ---------------------------------------------------------------------------
__global__ void __launch_bounds__(256) cvt_all(
    const float* __restrict__ noisy, const float* __restrict__ x,
    const float* __restrict__ Wq1, const float* __restrict__ Wk1,
    const float* __restrict__ Wq2, const float* __restrict__ Wk2,
    const float* __restrict__ Wv, const float* __restrict__ Wo) {
    int bid = blockIdx.x;
    const float* src; __half* dst; float alpha = 1.0f; int i;
    if (bid < 8192) {
        src = (bid < 4096) ? noisy : x;
        dst = (bid < 4096) ? g_nh : g_xh;
        i = (bid & 4095) * 256 + threadIdx.x;
    } else {
        int wb = bid - 8192;
        switch (wb >> 10) {
            case 0: src = Wq1; dst = g_wq1; alpha = QSCALE; break;
            case 1: src = Wk1; dst = g_wk1; break;
            case 2: src = Wq2; dst = g_wq2; alpha = QSCALE; break;
            case 3: src = Wk2; dst = g_wk2; break;
            case 4: src = Wv;  dst = g_wv;  break;
            default: src = Wo; dst = g_wo;  break;
        }
        i = (wb & 1023) * 256 + threadIdx.x;
    }
    float4 v = ((const float4*)src)[i];
    uint2 o;
    o.x = pack_h2(v.x * alpha, v.y * alpha);
    o.y = pack_h2(v.z * alpha, v.w * alpha);
    ((uint2*)dst)[i] = o;
}

// ---------------------------------------------------------------------------
// lambda = exp(sum lq1*lk1) - exp(sum lq2*lk2) + LAMBDA_INIT
// ---------------------------------------------------------------------------
__global__ void lambda_kernel(const float* __restrict__ lq1, const float* __restrict__ lk1,
                              const float* __restrict__ lq2, const float* __restrict__ lk2) {
    int l = threadIdx.x;
    float a = lq1[l] * lk1[l] + lq1[l + 32] * lk1[l + 32];
    float b = lq2[l] * lk2[l] + lq2[l + 32] * lk2[l + 32];
#pragma unroll
    for (int o = 16; o; o >>= 1) {
        a += __shfl_xor_sync(0xffffffffu, a, o);
        b += __shfl_xor_sync(0xffffffffu, b, o);
    }
    if (l == 0) g_lambda = expf(a) - expf(b) + LAMBDA_INIT;
}

// ---------------------------------------------------------------------------
// fp16 GEMM: 3-stage cp.async (96KB, 2 CTAs/SM), 4 warps, 64x64 warp tiles
// (HMMA:LDSM = 4.0), ldmatrix + m16n8k16 HMMA (fp32 acc), 1 barrier/slab.
// C[m,n] = sum_k A[m,k] * W[n,k]; M=4096, N=1024, K=1024.
// smem: rows of 64 f16 (128B); 16B chunk c of row r stored at c^(r&7).
// ---------------------------------------------------------------------------
constexpr uint32_t GEMM_SMEM = 3 * 16384 * 2;   // 98304

template <bool HEADOUT>
__device__ __forceinline__ void mma_gemm_h(const __half* __restrict__ A,
                                           const __half* __restrict__ Wh,
                                           void* __restrict__ Oout) {
    extern __shared__ __align__(16) char dyn[];
    const int K = 1024;
    const uint32_t aS = (uint32_t)__cvta_generic_to_shared(dyn);
    const uint32_t bS = aS + 49152;

    int tid = threadIdx.x, lane = tid & 31, warp = tid >> 5;   // 4 warps
    int g = lane >> 2, tg = lane & 3;
    int wm = warp >> 1, wn = warp & 1;
    int m0 = blockIdx.y * 128, n0 = blockIdx.x * 128;
    int sw = lane & 7;

    int arow = (lane & 7) + (((lane >> 3) & 1) << 3);
    int ahi  = (lane >> 4) & 1;
    int brow = (lane & 7) + (((lane >> 4) & 1) << 3);
    int bhi  = (lane >> 3) & 1;

    auto stage = [&](int s) {
        int f = s - (s / 3) * 3;
        uint32_t ab = aS + f * 16384;
        uint32_t bb = bS + f * 16384;
#pragma unroll
        for (int it = 0; it < 8; it++) {
            int ch = tid + it * 128;               // 1024 chunks per operand
            int r = ch >> 3, c = ch & 7;
            uint32_t so = r * 128 + ((c ^ (r & 7)) << 4);
            CP_ASYNC16(ab + so, A + (size_t)(m0 + r) * K + s * 64 + c * 8);
            CP_ASYNC16(bb + so, Wh + (size_t)(n0 + r) * K + s * 64 + c * 8);
        }
        CP_COMMIT();
    };

    float acc[4][8][4] = {};

    stage(0);
    stage(1);

    for (int i = 0; i < 16; i++) {
        if (i < 15) asm volatile("cp.async.wait_group 1;");
        else        asm volatile("cp.async.wait_group 0;");
        __syncthreads();               // tile i visible; buffer (i+2)%3 free
        if (i + 2 < 16) stage(i + 2);

        int f = i - (i / 3) * 3;
        uint32_t ab = aS + f * 16384;
        uint32_t bb = bS + f * 16384;

#pragma unroll
        for (int kc = 0; kc < 4; kc++) {
            uint32_t af[4][4];
#pragma unroll
            for (int mt = 0; mt < 4; mt++) {
                uint32_t ad = ab + (64 * wm + 16 * mt + arow) * 128 +
                              (((2 * kc + ahi) ^ sw) << 4);
                ldsm_x4(af[mt][0], af[mt][1], af[mt][2], af[mt][3], ad);
            }
#pragma unroll
            for (int p = 0; p < 4; p++) {
                uint32_t bd = bb + (64 * wn + 16 * p + brow) * 128 +
                              (((2 * kc + bhi) ^ sw) << 4);
                uint32_t b0, b1, b2, b3;
                ldsm_x4(b0, b1, b2, b3, bd);
                uint32_t bfa[2] = {b0, b1}, bfb[2] = {b2, b3};
#pragma unroll
                for (int mt = 0; mt < 4; mt++) {
                    mma_f16(acc[mt][2 * p], af[mt], bfa);
                    mma_f16(acc[mt][2 * p + 1], af[mt], bfb);
                }
            }
        }
    }

#pragma unroll
    for (int mt = 0; mt < 4; mt++) {
        int r1 = m0 + 64 * wm + 16 * mt + g;
#pragma unroll
        for (int nt = 0; nt < 8; nt++) {
            int cc = n0 + 64 * wn + 8 * nt + 2 * tg;
            float c0 = acc[mt][nt][0], c1 = acc[mt][nt][1];
            float c2 = acc[mt][nt][2], c3 = acc[mt][nt][3];
            if (HEADOUT) {
                int b = r1 >> 11, t = r1 & 2047;
                int h = cc >> 6, d = cc & 63;
                __half* base = (__half*)Oout + ((size_t)(b * kH + h) * kT + t) * kD + d;
                *(uint32_t*)base = pack_h2(c0, c1);
                *(uint32_t*)(base + 8 * kD) = pack_h2(c2, c3);
            } else {
                float* O = (float*)Oout;
                *(float2*)(O + (size_t)r1 * 1024 + cc) = make_float2(c0, c1);
                *(float2*)(O + (size_t)(r1 + 8) * 1024 + cc) = make_float2(c2, c3);
            }
        }
    }
}

__global__ void __launch_bounds__(128, 2) proj_gemm() {
    const __half* A; const __half* W; __half* O;
    switch (blockIdx.z) {
        case 0: A = g_nh; W = g_wq1; O = g_q1; break;   // QSCALE folded into g_wq1
        case 1: A = g_nh; W = g_wk1; O = g_k1; break;
        case 2: A = g_xh; W = g_wq2; O = g_q2; break;   // QSCALE folded into g_wq2
        case 3: A = g_xh; W = g_wk2; O = g_k2; break;
        default: A = g_nh; W = g_wv; O = g_v; break;
    }
    mma_gemm_h<true>(A, W, O);
}

__global__ void __launch_bounds__(128, 2) out_gemm(float* __restrict__ out) {
    mma_gemm_h<false>(g_attn, g_wo, out);
}

// ---------------------------------------------------------------------------
// Single-branch attention, 32 q-rows per warp, 4 warps/CTA, 3-stage cp.async,
// software-pipelined halves: S(keys 0-31) -> exp(A)||S(keys 32-63) ->
// PV(A)||exp(B) -> PV(B). Every scalar exp window has an independent HMMA
// stream to interleave with. l-sums on the FMA pipe.
// Grid (16 qtiles of 128 rows, 32 bh, 2 branches), 128 threads, 2 CTAs/SM.
// ---------------------------------------------------------------------------
constexpr int ATB_SMEM = 3 * 2 * 64 * 64 * 2;   // 49152 bytes (K + V, 3 stages)

__global__ void __launch_bounds__(128, 2) diffattn_branch() {
    extern __shared__ __align__(16) char dyn[];
    const uint32_t kS = (uint32_t)__cvta_generic_to_shared(dyn);
    const uint32_t vS = kS + 24576;

    int tid = threadIdx.x, lane = tid & 31, warp = tid >> 5;   // warp 0..3
    int g = lane >> 2, tg = lane & 3;
    int bh = blockIdx.y, qt = blockIdx.x, z = blockIdx.z;
    int sw = lane & 7;

    int brow = (lane & 7) + (((lane >> 4) & 1) << 3);
    int bhi  = (lane >> 3) & 1;
    int vrow = (lane & 7) + (((lane >> 3) & 1) << 3);
    int vhi  = (lane >> 4) & 1;

    const __half* Qg = (z ? g_q2 : g_q1) + ((size_t)bh * kT + qt * 128 + 32 * warp + g) * kD;
    const __half* Kb = (z ? g_k2 : g_k1) + (size_t)bh * kT * kD;
    const __half* Vb = g_v + (size_t)bh * kT * kD;
    float* pv = z ? g_pv2 : g_pv1;
    float* lv = z ? g_l2 : g_l1;

    // ---- Q fragments: 2 m-tiles x 4 k16-groups, registers for whole CTA ----
    uint32_t aq[2][4][4];
    {
        const uint32_t* qp = (const uint32_t*)Qg;   // row stride 32 u32
#pragma unroll
        for (int mt = 0; mt < 2; mt++) {
            const uint32_t* q0 = qp + (16 * mt) * 32;
            const uint32_t* q8 = q0 + 8 * 32;
#pragma unroll
            for (int k16 = 0; k16 < 4; k16++) {
                aq[mt][k16][0] = q0[k16 * 8 + tg];
                aq[mt][k16][1] = q8[k16 * 8 + tg];
                aq[mt][k16][2] = q0[k16 * 8 + tg + 4];
                aq[mt][k16][3] = q8[k16 * 8 + tg + 4];
            }
        }
    }

    auto stage = [&](int kt) {
        int f = kt - (kt / 3) * 3;
        uint32_t o = f * 8192;
#pragma unroll
        for (int it = 0; it < 4; it++) {
            int ch = tid + it * 128;                // 512 chunks per operand
            int r = ch >> 3, c = ch & 7;
            uint32_t so = o + r * 128 + ((c ^ (r & 7)) << 4);
            CP_ASYNC16(kS + so, Kb + ((size_t)kt * 64 + r) * kD + c * 8);
            CP_ASYNC16(vS + so, Vb + ((size_t)kt * 64 + r) * kD + c * 8);
        }
        CP_COMMIT();
    };

    float acc[2][8][4] = {};
    float lac[4] = {};     // [mt*2 + half]: rows 32w+16mt+g, +8

    stage(0);
    stage(1);

    for (int kt = 0; kt < 32; kt++) {
        if (kt < 31) asm volatile("cp.async.wait_group 1;");
        else         asm volatile("cp.async.wait_group 0;");
        __syncthreads();               // tile kt visible; buffer (kt+2)%3 free
        if (kt + 2 < 32) stage(kt + 2);

        int f = kt - (kt / 3) * 3;
        uint32_t kb = kS + f * 8192, vb = vS + f * 8192;

        float s[2][8][4];
        uint32_t pu[2][8][2];

        // ---- S half A: keys 0..31 ----
#pragma unroll
        for (int mt = 0; mt < 2; mt++)
#pragma unroll
            for (int nt = 0; nt < 4; nt++)
#pragma unroll
                for (int r = 0; r < 4; r++) s[mt][nt][r] = 0.f;
#pragma unroll
        for (int kc = 0; kc < 4; kc++) {
            uint32_t csel = ((2 * kc + bhi) ^ sw) << 4;
#pragma unroll
            for (int p = 0; p < 2; p++) {
                uint32_t b0, b1, b2, b3;
                ldsm_x4(b0, b1, b2, b3, kb + (16 * p + brow) * 128 + csel);
                uint32_t bfa[2] = {b0, b1}, bfb[2] = {b2, b3};
#pragma unroll
                for (int mt = 0; mt < 2; mt++) {
                    mma_f16(s[mt][2 * p], aq[mt][kc], bfa);
                    mma_f16(s[mt][2 * p + 1], aq[mt][kc], bfb);
                }
            }
        }

        // ---- exp(A) (interleaves with S half B below) ----
#pragma unroll
        for (int mt = 0; mt < 2; mt++)
#pragma unroll
            for (int nt = 0; nt < 4; nt++) {
                float e0 = ex2f(s[mt][nt][0]), e1 = ex2f(s[mt][nt][1]);
                float e2 = ex2f(s[mt][nt][2]), e3 = ex2f(s[mt][nt][3]);
                lac[mt * 2 + 0] += e0 + e1;
                lac[mt * 2 + 1] += e2 + e3;
                pu[mt][nt][0] = pack_h2(e0, e1);
                pu[mt][nt][1] = pack_h2(e2, e3);
            }

        // ---- S half B: keys 32..63 ----
#pragma unroll
        for (int mt = 0; mt < 2; mt++)
#pragma unroll
            for (int nt = 4; nt < 8; nt++)
#pragma unroll
                for (int r = 0; r < 4; r++) s[mt][nt][r] = 0.f;
#pragma unroll
        for (int kc = 0; kc < 4; kc++) {
            uint32_t csel = ((2 * kc + bhi) ^ sw) << 4;
#pragma unroll
            for (int p = 2; p < 4; p++) {
                uint32_t b0, b1, b2, b3;
                ldsm_x4(b0, b1, b2, b3, kb + (16 * p + brow) * 128 + csel);
                uint32_t bfa[2] = {b0, b1}, bfb[2] = {b2, b3};
#pragma unroll
                for (int mt = 0; mt < 2; mt++) {
                    mma_f16(s[mt][2 * p], aq[mt][kc], bfa);
                    mma_f16(s[mt][2 * p + 1], aq[mt][kc], bfb);
                }
            }
        }

        // ---- PV half A (keys 0..31, interleaves with exp(B) below) ----
#pragma unroll
        for (int j = 0; j < 2; j++) {
            uint32_t rbase = vb + (16 * j + vrow) * 128;
#pragma unroll
            for (int p = 0; p < 4; p++) {
                uint32_t b0, b1, b2, b3;
                ldsm_x4_t(b0, b1, b2, b3, rbase + (((2 * p + vhi) ^ sw) << 4));
                uint32_t bfa[2] = {b0, b1}, bfb[2] = {b2, b3};
#pragma unroll
                for (int mt = 0; mt < 2; mt++) {
                    uint32_t A1[4] = {pu[mt][2 * j][0], pu[mt][2 * j][1],
                                      pu[mt][2 * j + 1][0], pu[mt][2 * j + 1][1]};
                    mma_f16(acc[mt][2 * p], A1, bfa);
                    mma_f16(acc[mt][2 * p + 1], A1, bfb);
                }
            }
        }

        // ---- exp(B) ----
#pragma unroll
        for (int mt = 0; mt < 2; mt++)
#pragma unroll
            for (int nt = 4; nt < 8; nt++) {
                float e0 = ex2f(s[mt][nt][0]), e1 = ex2f(s[mt][nt][1]);
                float e2 = ex2f(s[mt][nt][2]), e3 = ex2f(s[mt][nt][3]);
                lac[mt * 2 + 0] += e0 + e1;
                lac[mt * 2 + 1] += e2 + e3;
                pu[mt][nt][0] = pack_h2(e0, e1);
                pu[mt][nt][1] = pack_h2(e2, e3);
            }

        // ---- PV half B (keys 32..63) ----
#pragma unroll
        for (int j = 2; j < 4; j++) {
            uint32_t rbase = vb + (16 * j + vrow) * 128;
#pragma unroll
            for (int p = 0; p < 4; p++) {
                uint32_t b0, b1, b2, b3;
                ldsm_x4_t(b0, b1, b2, b3, rbase + (((2 * p + vhi) ^ sw) << 4));
                uint32_t bfa[2] = {b0, b1}, bfb[2] = {b2, b3};
#pragma unroll
                for (int mt = 0; mt < 2; mt++) {
                    uint32_t A1[4] = {pu[mt][2 * j][0], pu[mt][2 * j][1],
                                      pu[mt][2 * j + 1][0], pu[mt][2 * j + 1][1]};
                    mma_f16(acc[mt][2 * p], A1, bfa);
                    mma_f16(acc[mt][2 * p + 1], A1, bfb);
                }
            }
        }
    }

    // ---- epilogue: reduce l across tg group, write PV (fp32) + l ----
#pragma unroll
    for (int i = 0; i < 4; i++) {
        lac[i] += __shfl_xor_sync(0xffffffffu, lac[i], 1);
        lac[i] += __shfl_xor_sync(0xffffffffu, lac[i], 2);
    }
#pragma unroll
    for (int mt = 0; mt < 2; mt++) {
        int t = qt * 128 + 32 * warp + 16 * mt + g;
        float* dst = pv + ((size_t)bh * kT + t) * kD;
#pragma unroll
        for (int ntd = 0; ntd < 8; ntd++) {
            int d0 = 8 * ntd + 2 * tg;
            *(float2*)(dst + d0) = make_float2(acc[mt][ntd][0], acc[mt][ntd][1]);
            *(float2*)(dst + 8 * kD + d0) = make_float2(acc[mt][ntd][2], acc[mt][ntd][3]);
        }
        if (tg == 0) {
            lv[(size_t)bh * kT + t] = lac[mt * 2];
            lv[(size_t)bh * kT + t + 8] = lac[mt * 2 + 1];
        }
    }
}

// ---------------------------------------------------------------------------
// Combine: out = a1/l1 - lambda*a2/l2, RMSNorm over D, affine, (1-lam_init),
// write fp16 into [B,T,H,D] for the output GEMM. One warp per (bh,t) row.
// ---------------------------------------------------------------------------
__global__ void __launch_bounds__(256) combine(const float* __restrict__ subln) {
    int row = blockIdx.x * 8 + (threadIdx.x >> 5);   // over B*H*T = 65536
    int lane = threadIdx.x & 31;
    int bh = row >> 11, t = row & 2047;

    float i1 = 1.0f / g_l1[row];
    float i2 = 1.0f / g_l2[row];
    float lam = g_lambda;

    float2 a1 = ((const float2*)g_pv1)[(size_t)row * 32 + lane];
    float2 a2 = ((const float2*)g_pv2)[(size_t)row * 32 + lane];
    float v0 = a1.x * i1 - lam * (a2.x * i2);
    float v1 = a1.y * i1 - lam * (a2.y * i2);

    float ss = v0 * v0 + v1 * v1;
#pragma unroll
    for (int o = 16; o; o >>= 1) ss += __shfl_xor_sync(0xffffffffu, ss, o);
    float sc = rsqrtf(ss * (1.0f / 64.0f) + EPS) * (1.0f - LAMBDA_INIT);

    int d0 = 2 * lane;
    float w0 = subln[d0], w1 = subln[d0 + 1];
    int b = bh >> 4, h = bh & 15;
    __half* base = g_attn + ((size_t)(b * kT + t) * kH + h) * kD + d0;
    *(uint32_t*)base = pack_h2(v0 * sc * w0, v1 * sc * w1);
}

// ---------------------------------------------------------------------------
extern "C" void kernel_launch(void* const* d_in, const int* in_sizes, int n_in,
                              void* d_out, int out_size) {
    const float* noisy = (const float*)d_in[0];
    const float* x     = (const float*)d_in[1];
    const float* Wq1   = (const float*)d_in[2];
    const float* Wk1   = (const float*)d_in[3];
    const float* Wq2   = (const float*)d_in[4];
    const float* Wk2   = (const float*)d_in[5];
    const float* Wv    = (const float*)d_in[6];
    const float* Wout  = (const float*)d_in[7];
    const float* lq1   = (const float*)d_in[8];
    const float* lk1   = (const float*)d_in[9];
    const float* lq2   = (const float*)d_in[10];
    const float* lk2   = (const float*)d_in[11];
    const float* subln = (const float*)d_in[12];
    float* out = (float*)d_out;

    cudaFuncSetAttribute(proj_gemm, cudaFuncAttributeMaxDynamicSharedMemorySize, GEMM_SMEM);
    cudaFuncSetAttribute(out_gemm, cudaFuncAttributeMaxDynamicSharedMemorySize, GEMM_SMEM);
    cudaFuncSetAttribute(diffattn_branch, cudaFuncAttributeMaxDynamicSharedMemorySize, ATB_SMEM);

    cvt_all<<<14336, 256>>>(noisy, x, Wq1, Wk1, Wq2, Wk2, Wv, Wout);
    lambda_kernel<<<1, 32>>>(lq1, lk1, lq2, lk2);
    proj_gemm<<<dim3(8, 32, 5), 128, GEMM_SMEM>>>();
    diffattn_branch<<<dim3(16, 32, 2), 128, ATB_SMEM>>>();
    combine<<<8192, 256>>>(subln);
    out_gemm<<<dim3(8, 32), 128, GEMM_SMEM>>>(out);
}